// round 9
// baseline (speedup 1.0000x reference)
#include <cuda_runtime.h>
#include <math.h>

// ---------------------------------------------------------------------------
// SpikingYOLO pipeline (fp32). R9: conv reduction order switched to the XLA
// NHWC im2col order k = (ky, kx, ic) with ic INNERMOST, single FFMA chain per
// output (XLA canonicalizes convs to NHWC/HWIO; patch index = (ky*kw+kx)*C+ic).
//   conv1 (2->64, 3x3, s1, p1)   -> g_l1
//   LIF in-place                 -> spikes
//   conv2 (64->128, 3x3, s2, p1) -> g_l2   (NHWC-order chain)
//   LIF in-place
//   conv3 (128->256, 3x3, s2,p1) -> g_l3   (NHWC-order chain)
//   LIF + time-mean fused        -> g_pool
//   det conv 1x1 (256->255)      -> d_out  (k = ic ascending)
// LIF: contracted FMA form; bias added once after the sum.
// ---------------------------------------------------------------------------

__device__ float g_l1[41943040];   // 10*4*64*128*128
__device__ float g_l2[20971520];   // 10*4*128*64*64
__device__ float g_l3[10485760];   // 10*4*256*32*32
__device__ float g_pool[1048576];  // 4*256*32*32
__device__ float g_wt2[73728];     // conv2 weights as [kk][ic][oc] (9*64*128)
__device__ float g_wt3[294912];    // conv3 weights as [kk][ic][oc] (9*128*256)

// ---------------------------------------------------------------------------
// weight transpose: w[oc][ic][3][3] -> wT[kk][ic][oc], kk = ky*3+kx
// ---------------------------------------------------------------------------
__global__ void wtrans_kernel(const float* __restrict__ w, float* __restrict__ wT,
                              int OC, int IC)
{
    int i = blockIdx.x * 256 + threadIdx.x;
    int total = OC * IC * 9;
    if (i >= total) return;
    int oc = i / (IC * 9);
    int r  = i - oc * (IC * 9);
    int ic = r / 9;
    int kk = r - ic * 9;
    wT[(kk * IC + ic) * OC + oc] = w[i];
}

// ---------------------------------------------------------------------------
// conv1: 2 -> 64, 3x3, s1, p1. Input x [B,2,128,128,T].
// Chain order: (ky, kx, ic), ic innermost. One accumulator per output.
// ---------------------------------------------------------------------------
__global__ void __launch_bounds__(256) conv1_kernel(
    const float* __restrict__ x, const float* __restrict__ w1,
    const float* __restrict__ b1, float* __restrict__ out)
{
    __shared__ float s_in[2][18][20];
    __shared__ float s_w[18][64];
    __shared__ float s_b[64];

    const int img = blockIdx.z;           // img = t*4 + b
    const int b = img & 3, t = img >> 2;
    const int tyo = (blockIdx.x >> 3) * 16;
    const int txo = (blockIdx.x & 7) * 16;
    const int tid = threadIdx.x;

    // weights: w1 [64][2][3][3] -> s_w[k][oc], k = ic*9 + ky*3 + kx
    for (int i = tid; i < 1152; i += 256) {
        int oc = i / 18, k = i - oc * 18;
        s_w[k][oc] = w1[i];
    }
    if (tid < 64) s_b[tid] = b1[tid];
    for (int i = tid; i < 2 * 18 * 18; i += 256) {
        int ic = i / 324;
        int rem = i - ic * 324;
        int r = rem / 18, c = rem - r * 18;
        int gy = tyo - 1 + r, gx = txo - 1 + c;
        float v = 0.f;
        if (gy >= 0 && gy < 128 && gx >= 0 && gx < 128)
            v = x[(((b * 2 + ic) * 128 + gy) * 128 + gx) * 10 + t];
        s_in[ic][r][c] = v;
    }
    __syncthreads();

    const int tx = tid & 15, ty = tid >> 4;
    float acc[64];
    #pragma unroll
    for (int oc = 0; oc < 64; oc++) acc[oc] = 0.f;

    // sequential FFMA chain, k ascending in (ky, kx, ic) -- ic INNERMOST
    #pragma unroll
    for (int ky = 0; ky < 3; ky++) {
        #pragma unroll
        for (int kx = 0; kx < 3; kx++) {
            #pragma unroll
            for (int ic = 0; ic < 2; ic++) {
                float v = s_in[ic][ty + ky][tx + kx];
                const float4* wp = (const float4*)s_w[ic * 9 + ky * 3 + kx];
                #pragma unroll
                for (int q = 0; q < 16; q++) {
                    float4 wv = wp[q];
                    acc[q * 4 + 0] = __fmaf_rn(v, wv.x, acc[q * 4 + 0]);
                    acc[q * 4 + 1] = __fmaf_rn(v, wv.y, acc[q * 4 + 1]);
                    acc[q * 4 + 2] = __fmaf_rn(v, wv.z, acc[q * 4 + 2]);
                    acc[q * 4 + 3] = __fmaf_rn(v, wv.w, acc[q * 4 + 3]);
                }
            }
        }
    }

    size_t base = ((size_t)img * 64) * 16384 + (size_t)(tyo + ty) * 128 + (txo + tx);
    #pragma unroll
    for (int oc = 0; oc < 64; oc++)
        out[base + (size_t)oc * 16384] = __fadd_rn(acc[oc], s_b[oc]);
}

// ---------------------------------------------------------------------------
// LIF scan, in place. Contracted FMA form.
// ---------------------------------------------------------------------------
__global__ void lif_kernel(float* buf, int n_per_t)
{
    int n = blockIdx.x * 256 + threadIdx.x;
    if (n >= n_per_t) return;
    const float alpha = expf(-0.05f);
    const float beta  = expf(-0.2f);
    float syn = 0.f, mem = 0.f;
    #pragma unroll
    for (int t = 0; t < 10; t++) {
        float cur = buf[(size_t)t * n_per_t + n];
        syn = __fmaf_rn(beta, syn, cur);
        mem = __fmaf_rn(alpha, mem, syn);
        float sp = (mem >= 1.0f) ? 1.0f : 0.0f;
        mem = __fsub_rn(mem, sp);
        buf[(size_t)t * n_per_t + n] = sp;
    }
}

__global__ void lif_pool_kernel(const float* __restrict__ buf,
                                float* __restrict__ pool, int n_per_t)
{
    int n = blockIdx.x * 256 + threadIdx.x;
    if (n >= n_per_t) return;
    const float alpha = expf(-0.05f);
    const float beta  = expf(-0.2f);
    float syn = 0.f, mem = 0.f, sum = 0.f;
    #pragma unroll
    for (int t = 0; t < 10; t++) {
        float cur = buf[(size_t)t * n_per_t + n];
        syn = __fmaf_rn(beta, syn, cur);
        mem = __fmaf_rn(alpha, mem, syn);
        float sp = (mem >= 1.0f) ? 1.0f : 0.0f;
        mem = __fsub_rn(mem, sp);
        sum += sp;
    }
    pool[n] = sum / 10.0f;
}

// ---------------------------------------------------------------------------
// Stride-2 3x3 conv, NHWC chain order: kk=(ky,kx) OUTER, ic ascending inner.
// Block: 256 threads, 16x16 output px x 64 oc. Thread: 16 oc x 2x2 px,
// one accumulator per output. Per (kk, 8-ic chunk): stage 16x16 strided input
// samples + 8x64 weights in smem.
// wT layout: [kk][ic][oc].
// ---------------------------------------------------------------------------
template<int IC, int OC, int IH>
__global__ void __launch_bounds__(256) conv_s2_nhwc_kernel(
    const float* __restrict__ in, const float* __restrict__ wT,
    const float* __restrict__ bias, float* __restrict__ out)
{
    constexpr int OH = IH / 2;
    constexpr int TX = OH / 16;
    __shared__ float s_w[8][64];
    __shared__ float s_x[8][16][17];

    const int img = blockIdx.z;
    const int ocb = blockIdx.y * 64;
    const int tyo = (blockIdx.x / TX) * 16;
    const int txo = (blockIdx.x % TX) * 16;
    const int tid = threadIdx.x;
    const int ocg = tid >> 6;          // 0..3  (16 oc each)
    const int tpix = tid & 63;
    const int tpx = tpix & 7, tpy = tpix >> 3;

    float acc[16][2][2];
    #pragma unroll
    for (int j = 0; j < 16; j++) {
        acc[j][0][0] = 0.f; acc[j][0][1] = 0.f;
        acc[j][1][0] = 0.f; acc[j][1][1] = 0.f;
    }

    #pragma unroll 1
    for (int kk = 0; kk < 9; kk++) {
        const int ky = kk / 3, kx = kk - 3 * ky;
        #pragma unroll 1
        for (int icc = 0; icc < IC; icc += 8) {
            __syncthreads();
            // weights: s_w[ic_l][oc_l]
            #pragma unroll
            for (int i = tid; i < 512; i += 256) {
                int icl = i >> 6, ocl = i & 63;
                s_w[icl][ocl] = wT[(size_t)(kk * IC + icc + icl) * OC + ocb + ocl];
            }
            // input: strided samples for the 16x16 output tile
            #pragma unroll
            for (int i = tid; i < 2048; i += 256) {
                int icl = i >> 8, rem = i & 255;
                int oy = rem >> 4, ox = rem & 15;
                int iy = 2 * (tyo + oy) + ky - 1;
                int ix = 2 * (txo + ox) + kx - 1;
                float v = 0.f;
                if (iy >= 0 && iy < IH && ix >= 0 && ix < IH)
                    v = in[((size_t)(img * IC + icc + icl) * IH + iy) * IH + ix];
                s_x[icl][oy][ox] = v;
            }
            __syncthreads();

            #pragma unroll
            for (int ic = 0; ic < 8; ic++) {
                float v00 = s_x[ic][2 * tpy + 0][2 * tpx + 0];
                float v01 = s_x[ic][2 * tpy + 0][2 * tpx + 1];
                float v10 = s_x[ic][2 * tpy + 1][2 * tpx + 0];
                float v11 = s_x[ic][2 * tpy + 1][2 * tpx + 1];
                const float4* wv4 = (const float4*)&s_w[ic][ocg * 16];
                #pragma unroll
                for (int q = 0; q < 4; q++) {
                    float4 wv = wv4[q];
                    float wl[4] = {wv.x, wv.y, wv.z, wv.w};
                    #pragma unroll
                    for (int e = 0; e < 4; e++) {
                        int j = q * 4 + e;
                        acc[j][0][0] = __fmaf_rn(wl[e], v00, acc[j][0][0]);
                        acc[j][0][1] = __fmaf_rn(wl[e], v01, acc[j][0][1]);
                        acc[j][1][0] = __fmaf_rn(wl[e], v10, acc[j][1][0]);
                        acc[j][1][1] = __fmaf_rn(wl[e], v11, acc[j][1][1]);
                    }
                }
            }
        }
    }

    #pragma unroll
    for (int j = 0; j < 16; j++) {
        int oc = ocb + ocg * 16 + j;
        float bv = bias[oc];
        float* op = out + ((size_t)img * OC + oc) * (OH * OH);
        #pragma unroll
        for (int sy = 0; sy < 2; sy++) {
            #pragma unroll
            for (int sx = 0; sx < 2; sx++) {
                int oy = tyo + 2 * tpy + sy;
                int ox = txo + 2 * tpx + sx;
                op[oy * OH + ox] = __fadd_rn(acc[j][sy][sx], bv);
            }
        }
    }
}

// ---------------------------------------------------------------------------
// det conv: 1x1, 256 -> 255, on pooled [4][256][1024]. k = ic ascending.
// ---------------------------------------------------------------------------
__global__ void __launch_bounds__(256) det_kernel(
    const float* __restrict__ pool, const float* __restrict__ wd,
    const float* __restrict__ bd, float* __restrict__ out)
{
    __shared__ float s_a[64][17];
    __shared__ float s_b[16][64];

    const int bz  = blockIdx.z;
    const int ocb = blockIdx.y * 64;
    const int pxb = blockIdx.x * 64;
    const int tid = threadIdx.x;
    const int ol0 = (tid & 15) * 4;
    const int pl0 = (tid >> 4) * 4;

    float acc[4][4];
    #pragma unroll
    for (int i = 0; i < 4; i++)
        #pragma unroll
        for (int j = 0; j < 4; j++) acc[i][j] = 0.f;

    for (int k0 = 0; k0 < 256; k0 += 16) {
        __syncthreads();
        for (int i = tid; i < 1024; i += 256) {
            int oc_l = i >> 4, kk = i & 15;
            int oc = ocb + oc_l;
            s_a[oc_l][kk] = (oc < 255) ? wd[oc * 256 + k0 + kk] : 0.f;
        }
        for (int i = tid; i < 1024; i += 256) {
            int kk = i >> 6, px_l = i & 63;
            s_b[kk][px_l] = pool[((size_t)bz * 256 + k0 + kk) * 1024 + pxb + px_l];
        }
        __syncthreads();
        #pragma unroll
        for (int kk = 0; kk < 16; kk++) {
            float a0 = s_a[ol0 + 0][kk], a1 = s_a[ol0 + 1][kk];
            float a2 = s_a[ol0 + 2][kk], a3 = s_a[ol0 + 3][kk];
            float b0 = s_b[kk][pl0 + 0], b1 = s_b[kk][pl0 + 1];
            float b2 = s_b[kk][pl0 + 2], b3 = s_b[kk][pl0 + 3];
            acc[0][0] = __fmaf_rn(a0, b0, acc[0][0]); acc[0][1] = __fmaf_rn(a0, b1, acc[0][1]);
            acc[0][2] = __fmaf_rn(a0, b2, acc[0][2]); acc[0][3] = __fmaf_rn(a0, b3, acc[0][3]);
            acc[1][0] = __fmaf_rn(a1, b0, acc[1][0]); acc[1][1] = __fmaf_rn(a1, b1, acc[1][1]);
            acc[1][2] = __fmaf_rn(a1, b2, acc[1][2]); acc[1][3] = __fmaf_rn(a1, b3, acc[1][3]);
            acc[2][0] = __fmaf_rn(a2, b0, acc[2][0]); acc[2][1] = __fmaf_rn(a2, b1, acc[2][1]);
            acc[2][2] = __fmaf_rn(a2, b2, acc[2][2]); acc[2][3] = __fmaf_rn(a2, b3, acc[2][3]);
            acc[3][0] = __fmaf_rn(a3, b0, acc[3][0]); acc[3][1] = __fmaf_rn(a3, b1, acc[3][1]);
            acc[3][2] = __fmaf_rn(a3, b2, acc[3][2]); acc[3][3] = __fmaf_rn(a3, b3, acc[3][3]);
        }
    }

    #pragma unroll
    for (int i = 0; i < 4; i++) {
        int oc = ocb + ol0 + i;
        if (oc >= 255) continue;
        float bv = bd[oc];
        #pragma unroll
        for (int j = 0; j < 4; j++)
            out[((size_t)bz * 255 + oc) * 1024 + pxb + pl0 + j] =
                __fadd_rn(acc[i][j], bv);
    }
}

// ---------------------------------------------------------------------------
extern "C" void kernel_launch(void* const* d_in, const int* in_sizes, int n_in,
                              void* d_out, int out_size)
{
    const float* x  = (const float*)d_in[0];
    const float* w1 = (const float*)d_in[1];
    const float* b1 = (const float*)d_in[2];
    const float* w2 = (const float*)d_in[3];
    const float* b2 = (const float*)d_in[4];
    const float* w3 = (const float*)d_in[5];
    const float* b3 = (const float*)d_in[6];
    const float* wd = (const float*)d_in[7];
    const float* bd = (const float*)d_in[8];
    float* out = (float*)d_out;

    float *l1, *l2, *l3, *pl, *wt2, *wt3;
    cudaGetSymbolAddress((void**)&l1, g_l1);
    cudaGetSymbolAddress((void**)&l2, g_l2);
    cudaGetSymbolAddress((void**)&l3, g_l3);
    cudaGetSymbolAddress((void**)&pl, g_pool);
    cudaGetSymbolAddress((void**)&wt2, g_wt2);
    cudaGetSymbolAddress((void**)&wt3, g_wt3);

    // weight transposes to [kk][ic][oc]
    wtrans_kernel<<<(73728 + 255) / 256, 256>>>(w2, wt2, 128, 64);
    wtrans_kernel<<<(294912 + 255) / 256, 256>>>(w3, wt3, 256, 128);

    conv1_kernel<<<dim3(64, 1, 40), 256>>>(x, w1, b1, l1);
    lif_kernel<<<4194304 / 256, 256>>>(l1, 4194304);
    conv_s2_nhwc_kernel<64, 128, 128><<<dim3(16, 2, 40), 256>>>(l1, wt2, b2, l2);
    lif_kernel<<<2097152 / 256, 256>>>(l2, 2097152);
    conv_s2_nhwc_kernel<128, 256, 64><<<dim3(4, 4, 40), 256>>>(l2, wt3, b3, l3);
    lif_pool_kernel<<<1048576 / 256, 256>>>(l3, pl, 1048576);
    det_kernel<<<dim3(16, 4, 4), 256>>>(pl, wd, bd, out);
}

// round 11
// speedup vs baseline: 1.2731x; 1.2731x over previous
#include <cuda_runtime.h>
#include <math.h>
#include <stdint.h>

// ---------------------------------------------------------------------------
// SpikingYOLO (fp32, bit-exact vs XLA ref — conv chain k=(ky,kx,ic) ic-inner,
// single FMA chain per output, bias post-add, LIF FMA-contracted).
// R11: R10 design + compile fix (stdint include / unsigned int).
//   conv1+LIF fused (spikes written directly, all 10 t per thread);
//   conv_s2 double-buffered cp.async pipeline, 16-ic stages, 1 sync/stage.
// ---------------------------------------------------------------------------

__device__ float g_l1[41943040];   // spikes layer1: [t*4+b][64][128][128]
__device__ float g_l2[20971520];   // layer2 currents->spikes
__device__ float g_l3[10485760];   // layer3 currents
__device__ float g_pool[1048576];  // pooled
__device__ float g_wt2[73728];     // conv2 w as [kk][ic][oc]
__device__ float g_wt3[294912];    // conv3 w as [kk][ic][oc]

// cp.async 4B with zero-fill when pred==false
__device__ __forceinline__ void cp4(void* smem_dst, const void* gsrc, bool pred) {
    unsigned int s = (unsigned int)__cvta_generic_to_shared(smem_dst);
    int sz = pred ? 4 : 0;
    asm volatile("cp.async.ca.shared.global [%0], [%1], 4, %2;\n"
                 :: "r"(s), "l"(gsrc), "r"(sz));
}
__device__ __forceinline__ void cp_commit() {
    asm volatile("cp.async.commit_group;\n");
}
__device__ __forceinline__ void cp_wait0() {
    asm volatile("cp.async.wait_group 0;\n");
}

// ---------------------------------------------------------------------------
// weight transpose: w[oc][ic][3][3] -> wT[kk][ic][oc], kk = ky*3+kx
// ---------------------------------------------------------------------------
__global__ void wtrans_kernel(const float* __restrict__ w, float* __restrict__ wT,
                              int OC, int IC)
{
    int i = blockIdx.x * 256 + threadIdx.x;
    int total = OC * IC * 9;
    if (i >= total) return;
    int oc = i / (IC * 9);
    int r  = i - oc * (IC * 9);
    int ic = r / 9;
    int kk = r - ic * 9;
    wT[(kk * IC + ic) * OC + oc] = w[i];
}

// ---------------------------------------------------------------------------
// FUSED conv1 (2->64, 3x3, s1, p1) + LIF. Input x [4][2][128][128][10].
// Block: 256 threads = 16x16 px; grid (64 tiles, 8 oc-groups, 4 batch).
// Thread: 8 oc x 10 t accumulators; chain (ky,kx,ic) ic-inner per (oc,t);
// then LIF over t in registers; writes spikes to g_l1 [t*4+b][oc][y][x].
// ---------------------------------------------------------------------------
__global__ void __launch_bounds__(256) conv1_lif_kernel(
    const float* __restrict__ x, const float* __restrict__ w1,
    const float* __restrict__ b1, float* __restrict__ out)
{
    __shared__ float s_in[2][18][18][10];
    __shared__ float s_w[18][8];

    const int b   = blockIdx.z;
    const int ocb = blockIdx.y * 8;
    const int tyo = (blockIdx.x >> 3) * 16;
    const int txo = (blockIdx.x & 7) * 16;
    const int tid = threadIdx.x;

    // weights: w1 [64][2][3][3] -> s_w[k][ocl], k = ic*9 + ky*3 + kx
    if (tid < 144) {
        int ocl = tid / 18, k = tid - ocl * 18;
        s_w[k][ocl] = w1[(ocb + ocl) * 18 + k];
    }
    // input tile with halo, all 10 t
    for (int i = tid; i < 2 * 18 * 18; i += 256) {
        int ic = i / 324;
        int rem = i - ic * 324;
        int r = rem / 18, c = rem - r * 18;
        int gy = tyo - 1 + r, gx = txo - 1 + c;
        float2* sd = (float2*)s_in[ic][r][c];
        if (gy >= 0 && gy < 128 && gx >= 0 && gx < 128) {
            const float2* gp =
                (const float2*)(x + (size_t)(((b * 2 + ic) * 128 + gy) * 128 + gx) * 10);
            #pragma unroll
            for (int q = 0; q < 5; q++) sd[q] = gp[q];
        } else {
            #pragma unroll
            for (int q = 0; q < 5; q++) sd[q] = make_float2(0.f, 0.f);
        }
    }
    __syncthreads();

    const int tx = tid & 15, ty = tid >> 4;
    float acc[8][10];
    #pragma unroll
    for (int j = 0; j < 8; j++)
        #pragma unroll
        for (int t = 0; t < 10; t++) acc[j][t] = 0.f;

    // chain: k ascending in (ky, kx, ic) — ic INNERMOST
    #pragma unroll 1
    for (int ky = 0; ky < 3; ky++) {
        #pragma unroll
        for (int kx = 0; kx < 3; kx++) {
            #pragma unroll
            for (int ic = 0; ic < 2; ic++) {
                float v[10];
                const float2* vp = (const float2*)s_in[ic][ty + ky][tx + kx];
                #pragma unroll
                for (int q = 0; q < 5; q++) {
                    float2 vv = vp[q];
                    v[2 * q] = vv.x; v[2 * q + 1] = vv.y;
                }
                const int k = ic * 9 + ky * 3 + kx;
                #pragma unroll
                for (int j = 0; j < 8; j++) {
                    float wv = s_w[k][j];
                    #pragma unroll
                    for (int t = 0; t < 10; t++)
                        acc[j][t] = __fmaf_rn(v[t], wv, acc[j][t]);
                }
            }
        }
    }

    const float alpha = expf(-0.05f);
    const float beta  = expf(-0.2f);
    const size_t pxo = (size_t)(tyo + ty) * 128 + (txo + tx);
    #pragma unroll
    for (int j = 0; j < 8; j++) {
        float bv = b1[ocb + j];
        float syn = 0.f, mem = 0.f;
        #pragma unroll
        for (int t = 0; t < 10; t++) {
            float cur = __fadd_rn(acc[j][t], bv);
            syn = __fmaf_rn(beta, syn, cur);
            mem = __fmaf_rn(alpha, mem, syn);
            float sp = (mem >= 1.0f) ? 1.0f : 0.0f;
            mem = __fsub_rn(mem, sp);
            out[((size_t)(t * 4 + b) * 64 + ocb + j) * 16384 + pxo] = sp;
        }
    }
}

// ---------------------------------------------------------------------------
// LIF scan, in place (layer 2). Contracted FMA form.
// ---------------------------------------------------------------------------
__global__ void lif_kernel(float* buf, int n_per_t)
{
    int n = blockIdx.x * 256 + threadIdx.x;
    if (n >= n_per_t) return;
    const float alpha = expf(-0.05f);
    const float beta  = expf(-0.2f);
    float syn = 0.f, mem = 0.f;
    #pragma unroll
    for (int t = 0; t < 10; t++) {
        float cur = buf[(size_t)t * n_per_t + n];
        syn = __fmaf_rn(beta, syn, cur);
        mem = __fmaf_rn(alpha, mem, syn);
        float sp = (mem >= 1.0f) ? 1.0f : 0.0f;
        mem = __fsub_rn(mem, sp);
        buf[(size_t)t * n_per_t + n] = sp;
    }
}

__global__ void lif_pool_kernel(const float* __restrict__ buf,
                                float* __restrict__ pool, int n_per_t)
{
    int n = blockIdx.x * 256 + threadIdx.x;
    if (n >= n_per_t) return;
    const float alpha = expf(-0.05f);
    const float beta  = expf(-0.2f);
    float syn = 0.f, mem = 0.f, sum = 0.f;
    #pragma unroll
    for (int t = 0; t < 10; t++) {
        float cur = buf[(size_t)t * n_per_t + n];
        syn = __fmaf_rn(beta, syn, cur);
        mem = __fmaf_rn(alpha, mem, syn);
        float sp = (mem >= 1.0f) ? 1.0f : 0.0f;
        mem = __fsub_rn(mem, sp);
        sum += sp;
    }
    pool[n] = sum / 10.0f;
}

// ---------------------------------------------------------------------------
// Stride-2 3x3 conv, NHWC chain order (kk outer, ic inner ascending).
// Double-buffered cp.async pipeline, 16-ic stages, one sync per stage.
// Block: 256 threads, 16x16 output px x 64 oc; thread: 16 oc x 2x2 px.
// wT layout: [kk][ic][oc].
// ---------------------------------------------------------------------------
template<int IC, int OC, int IH>
__global__ void __launch_bounds__(256) conv_s2_nhwc_kernel(
    const float* __restrict__ in, const float* __restrict__ wT,
    const float* __restrict__ bias, float* __restrict__ out)
{
    constexpr int OH = IH / 2;
    constexpr int TX = OH / 16;
    constexpr int NCH = IC / 16;         // 16-ic chunks per kk
    constexpr int NS = 9 * NCH;          // total stages

    __shared__ float s_w[2][16][64];
    __shared__ float s_x[2][16][16][17];

    const int img = blockIdx.z;
    const int ocb = blockIdx.y * 64;
    const int tyo = (blockIdx.x / TX) * 16;
    const int txo = (blockIdx.x % TX) * 16;
    const int tid = threadIdx.x;
    const int ocg = tid >> 6;            // 0..3 (16 oc each)
    const int tpix = tid & 63;
    const int tpx = tpix & 7, tpy = tpix >> 3;

    // staging coordinates (fixed per thread; only kk/icc vary per stage)
    const int soy = tid >> 4, sox = tid & 15;

    float acc[16][2][2];
    #pragma unroll
    for (int j = 0; j < 16; j++) {
        acc[j][0][0] = 0.f; acc[j][0][1] = 0.f;
        acc[j][1][0] = 0.f; acc[j][1][1] = 0.f;
    }

    // stage loader: stage s -> buffer bsel
    auto stage_load = [&](int s, int bsel) {
        int kk  = s / NCH;
        int icc = (s - kk * NCH) * 16;
        int ky = kk / 3, kx = kk - 3 * ky;
        int iy = 2 * (tyo + soy) + ky - 1;
        int ix = 2 * (txo + sox) + kx - 1;
        bool pred = (iy >= 0) && (iy < IH) && (ix >= 0) && (ix < IH);
        const float* g = pred
            ? in + ((size_t)(img * IC + icc) * IH + iy) * IH + ix
            : in;
        float* sd = &s_x[bsel][0][soy][sox];
        #pragma unroll
        for (int i = 0; i < 16; i++)
            cp4(sd + i * 272, g + (size_t)i * (IH * IH), pred);
        #pragma unroll
        for (int i = 0; i < 4; i++) {
            int idx = tid + i * 256;
            int icl = idx >> 6, ocl = idx & 63;
            cp4(&s_w[bsel][icl][ocl],
                wT + (size_t)(kk * IC + icc + icl) * OC + ocb + ocl, true);
        }
        cp_commit();
    };

    stage_load(0, 0);
    cp_wait0();
    __syncthreads();

    #pragma unroll 1
    for (int s = 0; s < NS; s++) {
        const int cb = s & 1;
        if (s + 1 < NS) stage_load(s + 1, (s + 1) & 1);

        #pragma unroll
        for (int ic = 0; ic < 16; ic++) {
            float v00 = s_x[cb][ic][2 * tpy + 0][2 * tpx + 0];
            float v01 = s_x[cb][ic][2 * tpy + 0][2 * tpx + 1];
            float v10 = s_x[cb][ic][2 * tpy + 1][2 * tpx + 0];
            float v11 = s_x[cb][ic][2 * tpy + 1][2 * tpx + 1];
            const float4* wv4 = (const float4*)&s_w[cb][ic][ocg * 16];
            #pragma unroll
            for (int q = 0; q < 4; q++) {
                float4 wv = wv4[q];
                float wl[4] = {wv.x, wv.y, wv.z, wv.w};
                #pragma unroll
                for (int e = 0; e < 4; e++) {
                    int j = q * 4 + e;
                    acc[j][0][0] = __fmaf_rn(wl[e], v00, acc[j][0][0]);
                    acc[j][0][1] = __fmaf_rn(wl[e], v01, acc[j][0][1]);
                    acc[j][1][0] = __fmaf_rn(wl[e], v10, acc[j][1][0]);
                    acc[j][1][1] = __fmaf_rn(wl[e], v11, acc[j][1][1]);
                }
            }
        }

        if (s + 1 < NS) {
            cp_wait0();
            __syncthreads();
        }
    }

    #pragma unroll
    for (int j = 0; j < 16; j++) {
        int oc = ocb + ocg * 16 + j;
        float bv = bias[oc];
        float* op = out + ((size_t)img * OC + oc) * (OH * OH);
        #pragma unroll
        for (int sy = 0; sy < 2; sy++) {
            #pragma unroll
            for (int sx = 0; sx < 2; sx++) {
                int oy = tyo + 2 * tpy + sy;
                int ox = txo + 2 * tpx + sx;
                op[oy * OH + ox] = __fadd_rn(acc[j][sy][sx], bv);
            }
        }
    }
}

// ---------------------------------------------------------------------------
// det conv: 1x1, 256 -> 255, on pooled [4][256][1024]. k = ic ascending.
// ---------------------------------------------------------------------------
__global__ void __launch_bounds__(256) det_kernel(
    const float* __restrict__ pool, const float* __restrict__ wd,
    const float* __restrict__ bd, float* __restrict__ out)
{
    __shared__ float s_a[64][17];
    __shared__ float s_b[16][64];

    const int bz  = blockIdx.z;
    const int ocb = blockIdx.y * 64;
    const int pxb = blockIdx.x * 64;
    const int tid = threadIdx.x;
    const int ol0 = (tid & 15) * 4;
    const int pl0 = (tid >> 4) * 4;

    float acc[4][4];
    #pragma unroll
    for (int i = 0; i < 4; i++)
        #pragma unroll
        for (int j = 0; j < 4; j++) acc[i][j] = 0.f;

    for (int k0 = 0; k0 < 256; k0 += 16) {
        __syncthreads();
        for (int i = tid; i < 1024; i += 256) {
            int oc_l = i >> 4, kk = i & 15;
            int oc = ocb + oc_l;
            s_a[oc_l][kk] = (oc < 255) ? wd[oc * 256 + k0 + kk] : 0.f;
        }
        for (int i = tid; i < 1024; i += 256) {
            int kk = i >> 6, px_l = i & 63;
            s_b[kk][px_l] = pool[((size_t)bz * 256 + k0 + kk) * 1024 + pxb + px_l];
        }
        __syncthreads();
        #pragma unroll
        for (int kk = 0; kk < 16; kk++) {
            float a0 = s_a[ol0 + 0][kk], a1 = s_a[ol0 + 1][kk];
            float a2 = s_a[ol0 + 2][kk], a3 = s_a[ol0 + 3][kk];
            float b0 = s_b[kk][pl0 + 0], b1 = s_b[kk][pl0 + 1];
            float b2 = s_b[kk][pl0 + 2], b3 = s_b[kk][pl0 + 3];
            acc[0][0] = __fmaf_rn(a0, b0, acc[0][0]); acc[0][1] = __fmaf_rn(a0, b1, acc[0][1]);
            acc[0][2] = __fmaf_rn(a0, b2, acc[0][2]); acc[0][3] = __fmaf_rn(a0, b3, acc[0][3]);
            acc[1][0] = __fmaf_rn(a1, b0, acc[1][0]); acc[1][1] = __fmaf_rn(a1, b1, acc[1][1]);
            acc[1][2] = __fmaf_rn(a1, b2, acc[1][2]); acc[1][3] = __fmaf_rn(a1, b3, acc[1][3]);
            acc[2][0] = __fmaf_rn(a2, b0, acc[2][0]); acc[2][1] = __fmaf_rn(a2, b1, acc[2][1]);
            acc[2][2] = __fmaf_rn(a2, b2, acc[2][2]); acc[2][3] = __fmaf_rn(a2, b3, acc[2][3]);
            acc[3][0] = __fmaf_rn(a3, b0, acc[3][0]); acc[3][1] = __fmaf_rn(a3, b1, acc[3][1]);
            acc[3][2] = __fmaf_rn(a3, b2, acc[3][2]); acc[3][3] = __fmaf_rn(a3, b3, acc[3][3]);
        }
    }

    #pragma unroll
    for (int i = 0; i < 4; i++) {
        int oc = ocb + ol0 + i;
        if (oc >= 255) continue;
        float bv = bd[oc];
        #pragma unroll
        for (int j = 0; j < 4; j++)
            out[((size_t)bz * 255 + oc) * 1024 + pxb + pl0 + j] =
                __fadd_rn(acc[i][j], bv);
    }
}

// ---------------------------------------------------------------------------
extern "C" void kernel_launch(void* const* d_in, const int* in_sizes, int n_in,
                              void* d_out, int out_size)
{
    const float* x  = (const float*)d_in[0];
    const float* w1 = (const float*)d_in[1];
    const float* b1 = (const float*)d_in[2];
    const float* w2 = (const float*)d_in[3];
    const float* b2 = (const float*)d_in[4];
    const float* w3 = (const float*)d_in[5];
    const float* b3 = (const float*)d_in[6];
    const float* wd = (const float*)d_in[7];
    const float* bd = (const float*)d_in[8];
    float* out = (float*)d_out;

    float *l1, *l2, *l3, *pl, *wt2, *wt3;
    cudaGetSymbolAddress((void**)&l1, g_l1);
    cudaGetSymbolAddress((void**)&l2, g_l2);
    cudaGetSymbolAddress((void**)&l3, g_l3);
    cudaGetSymbolAddress((void**)&pl, g_pool);
    cudaGetSymbolAddress((void**)&wt2, g_wt2);
    cudaGetSymbolAddress((void**)&wt3, g_wt3);

    wtrans_kernel<<<(73728 + 255) / 256, 256>>>(w2, wt2, 128, 64);
    wtrans_kernel<<<(294912 + 255) / 256, 256>>>(w3, wt3, 256, 128);

    // fused conv1 + LIF1: writes spikes directly
    conv1_lif_kernel<<<dim3(64, 8, 4), 256>>>(x, w1, b1, l1);
    // conv2: 64->128
    conv_s2_nhwc_kernel<64, 128, 128><<<dim3(16, 2, 40), 256>>>(l1, wt2, b2, l2);
    lif_kernel<<<2097152 / 256, 256>>>(l2, 2097152);
    // conv3: 128->256
    conv_s2_nhwc_kernel<128, 256, 64><<<dim3(4, 4, 40), 256>>>(l2, wt3, b3, l3);
    lif_pool_kernel<<<1048576 / 256, 256>>>(l3, pl, 1048576);
    det_kernel<<<dim3(16, 4, 4), 256>>>(pl, wd, bd, out);
}

// round 12
// speedup vs baseline: 1.6629x; 1.3062x over previous
#include <cuda_runtime.h>
#include <math.h>
#include <stdint.h>

// ---------------------------------------------------------------------------
// SpikingYOLO (fp32, bit-exact vs XLA ref — conv chain k=(ky,kx,ic) ic-inner,
// single FMA chain per output, bias post-add, LIF FMA-contracted).
// R12: conv_s2 inner loop re-mapped: thread = 16 oc x 4 CONSECUTIVE px,
//      inputs via one LDS.128/ic (conflict-free [ic][16][16] layout),
//      float4 output stores. LDS wavefronts per ic: ~8 (was ~18-20).
// ---------------------------------------------------------------------------

__device__ float g_l1[41943040];   // spikes layer1: [t*4+b][64][128][128]
__device__ float g_l2[20971520];   // layer2 currents->spikes
__device__ float g_l3[10485760];   // layer3 currents
__device__ float g_pool[1048576];  // pooled
__device__ float g_wt2[73728];     // conv2 w as [kk][ic][oc]
__device__ float g_wt3[294912];    // conv3 w as [kk][ic][oc]

// cp.async 4B with zero-fill when pred==false
__device__ __forceinline__ void cp4(void* smem_dst, const void* gsrc, bool pred) {
    unsigned int s = (unsigned int)__cvta_generic_to_shared(smem_dst);
    int sz = pred ? 4 : 0;
    asm volatile("cp.async.ca.shared.global [%0], [%1], 4, %2;\n"
                 :: "r"(s), "l"(gsrc), "r"(sz));
}
__device__ __forceinline__ void cp_commit() {
    asm volatile("cp.async.commit_group;\n");
}
__device__ __forceinline__ void cp_wait0() {
    asm volatile("cp.async.wait_group 0;\n");
}

// ---------------------------------------------------------------------------
// weight transpose: w[oc][ic][3][3] -> wT[kk][ic][oc], kk = ky*3+kx
// ---------------------------------------------------------------------------
__global__ void wtrans_kernel(const float* __restrict__ w, float* __restrict__ wT,
                              int OC, int IC)
{
    int i = blockIdx.x * 256 + threadIdx.x;
    int total = OC * IC * 9;
    if (i >= total) return;
    int oc = i / (IC * 9);
    int r  = i - oc * (IC * 9);
    int ic = r / 9;
    int kk = r - ic * 9;
    wT[(kk * IC + ic) * OC + oc] = w[i];
}

// ---------------------------------------------------------------------------
// FUSED conv1 (2->64, 3x3, s1, p1) + LIF. Input x [4][2][128][128][10].
// Block: 256 threads = 16x16 px; grid (64 tiles, 8 oc-groups, 4 batch).
// ---------------------------------------------------------------------------
__global__ void __launch_bounds__(256) conv1_lif_kernel(
    const float* __restrict__ x, const float* __restrict__ w1,
    const float* __restrict__ b1, float* __restrict__ out)
{
    __shared__ float s_in[2][18][18][10];
    __shared__ float s_w[18][8];

    const int b   = blockIdx.z;
    const int ocb = blockIdx.y * 8;
    const int tyo = (blockIdx.x >> 3) * 16;
    const int txo = (blockIdx.x & 7) * 16;
    const int tid = threadIdx.x;

    if (tid < 144) {
        int ocl = tid / 18, k = tid - ocl * 18;
        s_w[k][ocl] = w1[(ocb + ocl) * 18 + k];
    }
    for (int i = tid; i < 2 * 18 * 18; i += 256) {
        int ic = i / 324;
        int rem = i - ic * 324;
        int r = rem / 18, c = rem - r * 18;
        int gy = tyo - 1 + r, gx = txo - 1 + c;
        float2* sd = (float2*)s_in[ic][r][c];
        if (gy >= 0 && gy < 128 && gx >= 0 && gx < 128) {
            const float2* gp =
                (const float2*)(x + (size_t)(((b * 2 + ic) * 128 + gy) * 128 + gx) * 10);
            #pragma unroll
            for (int q = 0; q < 5; q++) sd[q] = gp[q];
        } else {
            #pragma unroll
            for (int q = 0; q < 5; q++) sd[q] = make_float2(0.f, 0.f);
        }
    }
    __syncthreads();

    const int tx = tid & 15, ty = tid >> 4;
    float acc[8][10];
    #pragma unroll
    for (int j = 0; j < 8; j++)
        #pragma unroll
        for (int t = 0; t < 10; t++) acc[j][t] = 0.f;

    // chain: k ascending in (ky, kx, ic) — ic INNERMOST
    #pragma unroll 1
    for (int ky = 0; ky < 3; ky++) {
        #pragma unroll
        for (int kx = 0; kx < 3; kx++) {
            #pragma unroll
            for (int ic = 0; ic < 2; ic++) {
                float v[10];
                const float2* vp = (const float2*)s_in[ic][ty + ky][tx + kx];
                #pragma unroll
                for (int q = 0; q < 5; q++) {
                    float2 vv = vp[q];
                    v[2 * q] = vv.x; v[2 * q + 1] = vv.y;
                }
                const int k = ic * 9 + ky * 3 + kx;
                #pragma unroll
                for (int j = 0; j < 8; j++) {
                    float wv = s_w[k][j];
                    #pragma unroll
                    for (int t = 0; t < 10; t++)
                        acc[j][t] = __fmaf_rn(v[t], wv, acc[j][t]);
                }
            }
        }
    }

    const float alpha = expf(-0.05f);
    const float beta  = expf(-0.2f);
    const size_t pxo = (size_t)(tyo + ty) * 128 + (txo + tx);
    #pragma unroll
    for (int j = 0; j < 8; j++) {
        float bv = b1[ocb + j];
        float syn = 0.f, mem = 0.f;
        #pragma unroll
        for (int t = 0; t < 10; t++) {
            float cur = __fadd_rn(acc[j][t], bv);
            syn = __fmaf_rn(beta, syn, cur);
            mem = __fmaf_rn(alpha, mem, syn);
            float sp = (mem >= 1.0f) ? 1.0f : 0.0f;
            mem = __fsub_rn(mem, sp);
            out[((size_t)(t * 4 + b) * 64 + ocb + j) * 16384 + pxo] = sp;
        }
    }
}

// ---------------------------------------------------------------------------
// LIF scan, in place (layer 2). Contracted FMA form.
// ---------------------------------------------------------------------------
__global__ void lif_kernel(float* buf, int n_per_t)
{
    int n = blockIdx.x * 256 + threadIdx.x;
    if (n >= n_per_t) return;
    const float alpha = expf(-0.05f);
    const float beta  = expf(-0.2f);
    float syn = 0.f, mem = 0.f;
    #pragma unroll
    for (int t = 0; t < 10; t++) {
        float cur = buf[(size_t)t * n_per_t + n];
        syn = __fmaf_rn(beta, syn, cur);
        mem = __fmaf_rn(alpha, mem, syn);
        float sp = (mem >= 1.0f) ? 1.0f : 0.0f;
        mem = __fsub_rn(mem, sp);
        buf[(size_t)t * n_per_t + n] = sp;
    }
}

__global__ void lif_pool_kernel(const float* __restrict__ buf,
                                float* __restrict__ pool, int n_per_t)
{
    int n = blockIdx.x * 256 + threadIdx.x;
    if (n >= n_per_t) return;
    const float alpha = expf(-0.05f);
    const float beta  = expf(-0.2f);
    float syn = 0.f, mem = 0.f, sum = 0.f;
    #pragma unroll
    for (int t = 0; t < 10; t++) {
        float cur = buf[(size_t)t * n_per_t + n];
        syn = __fmaf_rn(beta, syn, cur);
        mem = __fmaf_rn(alpha, mem, syn);
        float sp = (mem >= 1.0f) ? 1.0f : 0.0f;
        mem = __fsub_rn(mem, sp);
        sum += sp;
    }
    pool[n] = sum / 10.0f;
}

// ---------------------------------------------------------------------------
// Stride-2 3x3 conv, NHWC chain order (kk outer, ic inner ascending).
// Double-buffered cp.async pipeline, 16-ic stages, one sync per stage.
// Block: 256 threads = 16x16 output px x 64 oc.
// Thread: 16 oc x 4 CONSECUTIVE px (one row quad) -> input = 1 LDS.128/ic,
// conflict-free s_x[ic][16][16] (each 8-lane phase covers banks 0..31 once).
// wT layout: [kk][ic][oc].
// ---------------------------------------------------------------------------
template<int IC, int OC, int IH>
__global__ void __launch_bounds__(256, 2) conv_s2_nhwc_kernel(
    const float* __restrict__ in, const float* __restrict__ wT,
    const float* __restrict__ bias, float* __restrict__ out)
{
    constexpr int OH = IH / 2;
    constexpr int TX = OH / 16;
    constexpr int NCH = IC / 16;         // 16-ic chunks per kk
    constexpr int NS = 9 * NCH;          // total stages

    __shared__ float s_w[2][16][64];
    __shared__ float s_x[2][16][16][16];  // [buf][ic][oy][ox]

    const int img = blockIdx.z;
    const int ocb = blockIdx.y * 64;
    const int tyo = (blockIdx.x / TX) * 16;
    const int txo = (blockIdx.x % TX) * 16;
    const int tid = threadIdx.x;
    const int ocg = tid >> 6;            // 0..3 (16 oc each)
    const int tpix = tid & 63;
    const int oy = tpix >> 2;            // 0..15 output row
    const int qx = tpix & 3;             // 0..3  quad of 4 consecutive ox

    // staging coordinates
    const int soy = tid >> 4, sox = tid & 15;

    float acc[16][4];
    #pragma unroll
    for (int j = 0; j < 16; j++) {
        acc[j][0] = 0.f; acc[j][1] = 0.f; acc[j][2] = 0.f; acc[j][3] = 0.f;
    }

    // stage loader: stage s -> buffer bsel
    auto stage_load = [&](int s, int bsel) {
        int kk  = s / NCH;
        int icc = (s - kk * NCH) * 16;
        int ky = kk / 3, kx = kk - 3 * ky;
        int iy = 2 * (tyo + soy) + ky - 1;
        int ix = 2 * (txo + sox) + kx - 1;
        bool pred = (iy >= 0) && (iy < IH) && (ix >= 0) && (ix < IH);
        const float* g = pred
            ? in + ((size_t)(img * IC + icc) * IH + iy) * IH + ix
            : in;
        float* sd = &s_x[bsel][0][soy][sox];
        #pragma unroll
        for (int i = 0; i < 16; i++)
            cp4(sd + i * 256, g + (size_t)i * (IH * IH), pred);
        #pragma unroll
        for (int i = 0; i < 4; i++) {
            int idx = tid + i * 256;
            int icl = idx >> 6, ocl = idx & 63;
            cp4(&s_w[bsel][icl][ocl],
                wT + (size_t)(kk * IC + icc + icl) * OC + ocb + ocl, true);
        }
        cp_commit();
    };

    stage_load(0, 0);
    cp_wait0();
    __syncthreads();

    #pragma unroll 1
    for (int s = 0; s < NS; s++) {
        const int cb = s & 1;
        if (s + 1 < NS) stage_load(s + 1, (s + 1) & 1);

        #pragma unroll
        for (int ic = 0; ic < 16; ic++) {
            float4 v = *(const float4*)&s_x[cb][ic][oy][qx * 4];
            const float4* wv4 = (const float4*)&s_w[cb][ic][ocg * 16];
            #pragma unroll
            for (int q = 0; q < 4; q++) {
                float4 wv = wv4[q];
                float wl[4] = {wv.x, wv.y, wv.z, wv.w};
                #pragma unroll
                for (int e = 0; e < 4; e++) {
                    int j = q * 4 + e;
                    acc[j][0] = __fmaf_rn(wl[e], v.x, acc[j][0]);
                    acc[j][1] = __fmaf_rn(wl[e], v.y, acc[j][1]);
                    acc[j][2] = __fmaf_rn(wl[e], v.z, acc[j][2]);
                    acc[j][3] = __fmaf_rn(wl[e], v.w, acc[j][3]);
                }
            }
        }

        if (s + 1 < NS) {
            cp_wait0();
            __syncthreads();
        }
    }

    const int orow = tyo + oy;
    const int ocol = txo + qx * 4;
    #pragma unroll
    for (int j = 0; j < 16; j++) {
        int oc = ocb + ocg * 16 + j;
        float bv = bias[oc];
        float4 r;
        r.x = __fadd_rn(acc[j][0], bv);
        r.y = __fadd_rn(acc[j][1], bv);
        r.z = __fadd_rn(acc[j][2], bv);
        r.w = __fadd_rn(acc[j][3], bv);
        float* op = out + ((size_t)img * OC + oc) * (OH * OH);
        *(float4*)&op[orow * OH + ocol] = r;
    }
}

// ---------------------------------------------------------------------------
// det conv: 1x1, 256 -> 255, on pooled [4][256][1024]. k = ic ascending.
// ---------------------------------------------------------------------------
__global__ void __launch_bounds__(256) det_kernel(
    const float* __restrict__ pool, const float* __restrict__ wd,
    const float* __restrict__ bd, float* __restrict__ out)
{
    __shared__ float s_a[64][17];
    __shared__ float s_b[16][64];

    const int bz  = blockIdx.z;
    const int ocb = blockIdx.y * 64;
    const int pxb = blockIdx.x * 64;
    const int tid = threadIdx.x;
    const int ol0 = (tid & 15) * 4;
    const int pl0 = (tid >> 4) * 4;

    float acc[4][4];
    #pragma unroll
    for (int i = 0; i < 4; i++)
        #pragma unroll
        for (int j = 0; j < 4; j++) acc[i][j] = 0.f;

    for (int k0 = 0; k0 < 256; k0 += 16) {
        __syncthreads();
        for (int i = tid; i < 1024; i += 256) {
            int oc_l = i >> 4, kk = i & 15;
            int oc = ocb + oc_l;
            s_a[oc_l][kk] = (oc < 255) ? wd[oc * 256 + k0 + kk] : 0.f;
        }
        for (int i = tid; i < 1024; i += 256) {
            int kk = i >> 6, px_l = i & 63;
            s_b[kk][px_l] = pool[((size_t)bz * 256 + k0 + kk) * 1024 + pxb + px_l];
        }
        __syncthreads();
        #pragma unroll
        for (int kk = 0; kk < 16; kk++) {
            float a0 = s_a[ol0 + 0][kk], a1 = s_a[ol0 + 1][kk];
            float a2 = s_a[ol0 + 2][kk], a3 = s_a[ol0 + 3][kk];
            float b0 = s_b[kk][pl0 + 0], b1 = s_b[kk][pl0 + 1];
            float b2 = s_b[kk][pl0 + 2], b3 = s_b[kk][pl0 + 3];
            acc[0][0] = __fmaf_rn(a0, b0, acc[0][0]); acc[0][1] = __fmaf_rn(a0, b1, acc[0][1]);
            acc[0][2] = __fmaf_rn(a0, b2, acc[0][2]); acc[0][3] = __fmaf_rn(a0, b3, acc[0][3]);
            acc[1][0] = __fmaf_rn(a1, b0, acc[1][0]); acc[1][1] = __fmaf_rn(a1, b1, acc[1][1]);
            acc[1][2] = __fmaf_rn(a1, b2, acc[1][2]); acc[1][3] = __fmaf_rn(a1, b3, acc[1][3]);
            acc[2][0] = __fmaf_rn(a2, b0, acc[2][0]); acc[2][1] = __fmaf_rn(a2, b1, acc[2][1]);
            acc[2][2] = __fmaf_rn(a2, b2, acc[2][2]); acc[2][3] = __fmaf_rn(a2, b3, acc[2][3]);
            acc[3][0] = __fmaf_rn(a3, b0, acc[3][0]); acc[3][1] = __fmaf_rn(a3, b1, acc[3][1]);
            acc[3][2] = __fmaf_rn(a3, b2, acc[3][2]); acc[3][3] = __fmaf_rn(a3, b3, acc[3][3]);
        }
    }

    #pragma unroll
    for (int i = 0; i < 4; i++) {
        int oc = ocb + ol0 + i;
        if (oc >= 255) continue;
        float bv = bd[oc];
        #pragma unroll
        for (int j = 0; j < 4; j++)
            out[((size_t)bz * 255 + oc) * 1024 + pxb + pl0 + j] =
                __fadd_rn(acc[i][j], bv);
    }
}

// ---------------------------------------------------------------------------
extern "C" void kernel_launch(void* const* d_in, const int* in_sizes, int n_in,
                              void* d_out, int out_size)
{
    const float* x  = (const float*)d_in[0];
    const float* w1 = (const float*)d_in[1];
    const float* b1 = (const float*)d_in[2];
    const float* w2 = (const float*)d_in[3];
    const float* b2 = (const float*)d_in[4];
    const float* w3 = (const float*)d_in[5];
    const float* b3 = (const float*)d_in[6];
    const float* wd = (const float*)d_in[7];
    const float* bd = (const float*)d_in[8];
    float* out = (float*)d_out;

    float *l1, *l2, *l3, *pl, *wt2, *wt3;
    cudaGetSymbolAddress((void**)&l1, g_l1);
    cudaGetSymbolAddress((void**)&l2, g_l2);
    cudaGetSymbolAddress((void**)&l3, g_l3);
    cudaGetSymbolAddress((void**)&pl, g_pool);
    cudaGetSymbolAddress((void**)&wt2, g_wt2);
    cudaGetSymbolAddress((void**)&wt3, g_wt3);

    wtrans_kernel<<<(73728 + 255) / 256, 256>>>(w2, wt2, 128, 64);
    wtrans_kernel<<<(294912 + 255) / 256, 256>>>(w3, wt3, 256, 128);

    // fused conv1 + LIF1: writes spikes directly
    conv1_lif_kernel<<<dim3(64, 8, 4), 256>>>(x, w1, b1, l1);
    // conv2: 64->128
    conv_s2_nhwc_kernel<64, 128, 128><<<dim3(16, 2, 40), 256>>>(l1, wt2, b2, l2);
    lif_kernel<<<2097152 / 256, 256>>>(l2, 2097152);
    // conv3: 128->256
    conv_s2_nhwc_kernel<128, 256, 64><<<dim3(4, 4, 40), 256>>>(l2, wt3, b3, l3);
    lif_pool_kernel<<<1048576 / 256, 256>>>(l3, pl, 1048576);
    det_kernel<<<dim3(16, 4, 4), 256>>>(pl, wd, bd, out);
}

// round 14
// speedup vs baseline: 1.7276x; 1.0389x over previous
#include <cuda_runtime.h>
#include <math.h>
#include <stdint.h>

// ---------------------------------------------------------------------------
// SpikingYOLO (fp32, bit-exact vs XLA ref — conv chain k=(ky,kx,ic) ic-inner,
// single FMA chain per output, bias post-add, LIF FMA-contracted).
// R14 == R13 (infra failure last round; clean re-measure):
//   conv_s2 uses packed fma.rn.f32x2 — two independent oc-chains per
//   instruction (lane-wise fma.rn => bit-identical to scalar chains).
//   Halves FFMA issue count and fma-pipe occupancy.
// ---------------------------------------------------------------------------

__device__ float g_l1[41943040];   // spikes layer1: [t*4+b][64][128][128]
__device__ float g_l2[20971520];   // layer2 currents->spikes
__device__ float g_l3[10485760];   // layer3 currents
__device__ float g_pool[1048576];  // pooled
__device__ float g_wt2[73728];     // conv2 w as [kk][ic][oc]
__device__ float g_wt3[294912];    // conv3 w as [kk][ic][oc]

// cp.async 4B with zero-fill when pred==false
__device__ __forceinline__ void cp4(void* smem_dst, const void* gsrc, bool pred) {
    unsigned int s = (unsigned int)__cvta_generic_to_shared(smem_dst);
    int sz = pred ? 4 : 0;
    asm volatile("cp.async.ca.shared.global [%0], [%1], 4, %2;\n"
                 :: "r"(s), "l"(gsrc), "r"(sz));
}
__device__ __forceinline__ void cp_commit() {
    asm volatile("cp.async.commit_group;\n");
}
__device__ __forceinline__ void cp_wait0() {
    asm volatile("cp.async.wait_group 0;\n");
}

// packed f32x2 helpers (lane-wise fma.rn — bit-identical to scalar chains)
__device__ __forceinline__ void fma2(unsigned long long& d,
                                     unsigned long long a,
                                     unsigned long long b) {
    asm("fma.rn.f32x2 %0, %1, %2, %0;" : "+l"(d) : "l"(a), "l"(b));
}
__device__ __forceinline__ unsigned long long pack2(float lo, float hi) {
    unsigned long long r;
    asm("mov.b64 %0, {%1, %2};" : "=l"(r) : "f"(lo), "f"(hi));
    return r;
}
__device__ __forceinline__ void unpack2(unsigned long long p, float& lo, float& hi) {
    asm("mov.b64 {%0, %1}, %2;" : "=f"(lo), "=f"(hi) : "l"(p));
}

// ---------------------------------------------------------------------------
// weight transpose: w[oc][ic][3][3] -> wT[kk][ic][oc], kk = ky*3+kx
// ---------------------------------------------------------------------------
__global__ void wtrans_kernel(const float* __restrict__ w, float* __restrict__ wT,
                              int OC, int IC)
{
    int i = blockIdx.x * 256 + threadIdx.x;
    int total = OC * IC * 9;
    if (i >= total) return;
    int oc = i / (IC * 9);
    int r  = i - oc * (IC * 9);
    int ic = r / 9;
    int kk = r - ic * 9;
    wT[(kk * IC + ic) * OC + oc] = w[i];
}

// ---------------------------------------------------------------------------
// FUSED conv1 (2->64, 3x3, s1, p1) + LIF. Input x [4][2][128][128][10].
// ---------------------------------------------------------------------------
__global__ void __launch_bounds__(256) conv1_lif_kernel(
    const float* __restrict__ x, const float* __restrict__ w1,
    const float* __restrict__ b1, float* __restrict__ out)
{
    __shared__ float s_in[2][18][18][10];
    __shared__ float s_w[18][8];

    const int b   = blockIdx.z;
    const int ocb = blockIdx.y * 8;
    const int tyo = (blockIdx.x >> 3) * 16;
    const int txo = (blockIdx.x & 7) * 16;
    const int tid = threadIdx.x;

    if (tid < 144) {
        int ocl = tid / 18, k = tid - ocl * 18;
        s_w[k][ocl] = w1[(ocb + ocl) * 18 + k];
    }
    for (int i = tid; i < 2 * 18 * 18; i += 256) {
        int ic = i / 324;
        int rem = i - ic * 324;
        int r = rem / 18, c = rem - r * 18;
        int gy = tyo - 1 + r, gx = txo - 1 + c;
        float2* sd = (float2*)s_in[ic][r][c];
        if (gy >= 0 && gy < 128 && gx >= 0 && gx < 128) {
            const float2* gp =
                (const float2*)(x + (size_t)(((b * 2 + ic) * 128 + gy) * 128 + gx) * 10);
            #pragma unroll
            for (int q = 0; q < 5; q++) sd[q] = gp[q];
        } else {
            #pragma unroll
            for (int q = 0; q < 5; q++) sd[q] = make_float2(0.f, 0.f);
        }
    }
    __syncthreads();

    const int tx = tid & 15, ty = tid >> 4;
    float acc[8][10];
    #pragma unroll
    for (int j = 0; j < 8; j++)
        #pragma unroll
        for (int t = 0; t < 10; t++) acc[j][t] = 0.f;

    // chain: k ascending in (ky, kx, ic) — ic INNERMOST
    #pragma unroll 1
    for (int ky = 0; ky < 3; ky++) {
        #pragma unroll
        for (int kx = 0; kx < 3; kx++) {
            #pragma unroll
            for (int ic = 0; ic < 2; ic++) {
                float v[10];
                const float2* vp = (const float2*)s_in[ic][ty + ky][tx + kx];
                #pragma unroll
                for (int q = 0; q < 5; q++) {
                    float2 vv = vp[q];
                    v[2 * q] = vv.x; v[2 * q + 1] = vv.y;
                }
                const int k = ic * 9 + ky * 3 + kx;
                #pragma unroll
                for (int j = 0; j < 8; j++) {
                    float wv = s_w[k][j];
                    #pragma unroll
                    for (int t = 0; t < 10; t++)
                        acc[j][t] = __fmaf_rn(v[t], wv, acc[j][t]);
                }
            }
        }
    }

    const float alpha = expf(-0.05f);
    const float beta  = expf(-0.2f);
    const size_t pxo = (size_t)(tyo + ty) * 128 + (txo + tx);
    #pragma unroll
    for (int j = 0; j < 8; j++) {
        float bv = b1[ocb + j];
        float syn = 0.f, mem = 0.f;
        #pragma unroll
        for (int t = 0; t < 10; t++) {
            float cur = __fadd_rn(acc[j][t], bv);
            syn = __fmaf_rn(beta, syn, cur);
            mem = __fmaf_rn(alpha, mem, syn);
            float sp = (mem >= 1.0f) ? 1.0f : 0.0f;
            mem = __fsub_rn(mem, sp);
            out[((size_t)(t * 4 + b) * 64 + ocb + j) * 16384 + pxo] = sp;
        }
    }
}

// ---------------------------------------------------------------------------
// LIF scan, in place (layer 2). Contracted FMA form.
// ---------------------------------------------------------------------------
__global__ void lif_kernel(float* buf, int n_per_t)
{
    int n = blockIdx.x * 256 + threadIdx.x;
    if (n >= n_per_t) return;
    const float alpha = expf(-0.05f);
    const float beta  = expf(-0.2f);
    float syn = 0.f, mem = 0.f;
    #pragma unroll
    for (int t = 0; t < 10; t++) {
        float cur = buf[(size_t)t * n_per_t + n];
        syn = __fmaf_rn(beta, syn, cur);
        mem = __fmaf_rn(alpha, mem, syn);
        float sp = (mem >= 1.0f) ? 1.0f : 0.0f;
        mem = __fsub_rn(mem, sp);
        buf[(size_t)t * n_per_t + n] = sp;
    }
}

__global__ void lif_pool_kernel(const float* __restrict__ buf,
                                float* __restrict__ pool, int n_per_t)
{
    int n = blockIdx.x * 256 + threadIdx.x;
    if (n >= n_per_t) return;
    const float alpha = expf(-0.05f);
    const float beta  = expf(-0.2f);
    float syn = 0.f, mem = 0.f, sum = 0.f;
    #pragma unroll
    for (int t = 0; t < 10; t++) {
        float cur = buf[(size_t)t * n_per_t + n];
        syn = __fmaf_rn(beta, syn, cur);
        mem = __fmaf_rn(alpha, mem, syn);
        float sp = (mem >= 1.0f) ? 1.0f : 0.0f;
        mem = __fsub_rn(mem, sp);
        sum += sp;
    }
    pool[n] = sum / 10.0f;
}

// ---------------------------------------------------------------------------
// Stride-2 3x3 conv, NHWC chain order (kk outer, ic inner ascending).
// Packed f32x2: acc[8 oc-pairs][4 px] as b64; weights loaded as b64 pairs
// (adjacent oc in s_w); v duplicated per px via mov.b64.
// Per warp-ic: 5 LDS.128 + 4 packs + 32 fma2 (was 5 LDS + 64 FFMA).
// ---------------------------------------------------------------------------
template<int IC, int OC, int IH>
__global__ void __launch_bounds__(256, 2) conv_s2_nhwc_kernel(
    const float* __restrict__ in, const float* __restrict__ wT,
    const float* __restrict__ bias, float* __restrict__ out)
{
    constexpr int OH = IH / 2;
    constexpr int TX = OH / 16;
    constexpr int NCH = IC / 16;         // 16-ic chunks per kk
    constexpr int NS = 9 * NCH;          // total stages

    __shared__ float s_w[2][16][64];
    __shared__ float s_x[2][16][16][16];  // [buf][ic][oy][ox]

    const int img = blockIdx.z;
    const int ocb = blockIdx.y * 64;
    const int tyo = (blockIdx.x / TX) * 16;
    const int txo = (blockIdx.x % TX) * 16;
    const int tid = threadIdx.x;
    const int ocg = tid >> 6;            // 0..3 (16 oc each)
    const int tpix = tid & 63;
    const int oy = tpix >> 2;            // 0..15 output row
    const int qx = tpix & 3;             // 0..3  quad of 4 consecutive ox

    const int soy = tid >> 4, sox = tid & 15;

    // acc[p][px]: packed pair (oc 2p, oc 2p+1) chains — lane-wise fma.rn
    unsigned long long acc[8][4];
    const unsigned long long z2 = pack2(0.f, 0.f);
    #pragma unroll
    for (int p = 0; p < 8; p++) {
        acc[p][0] = z2; acc[p][1] = z2; acc[p][2] = z2; acc[p][3] = z2;
    }

    auto stage_load = [&](int s, int bsel) {
        int kk  = s / NCH;
        int icc = (s - kk * NCH) * 16;
        int ky = kk / 3, kx = kk - 3 * ky;
        int iy = 2 * (tyo + soy) + ky - 1;
        int ix = 2 * (txo + sox) + kx - 1;
        bool pred = (iy >= 0) && (iy < IH) && (ix >= 0) && (ix < IH);
        const float* g = pred
            ? in + ((size_t)(img * IC + icc) * IH + iy) * IH + ix
            : in;
        float* sd = &s_x[bsel][0][soy][sox];
        #pragma unroll
        for (int i = 0; i < 16; i++)
            cp4(sd + i * 256, g + (size_t)i * (IH * IH), pred);
        #pragma unroll
        for (int i = 0; i < 4; i++) {
            int idx = tid + i * 256;
            int icl = idx >> 6, ocl = idx & 63;
            cp4(&s_w[bsel][icl][ocl],
                wT + (size_t)(kk * IC + icc + icl) * OC + ocb + ocl, true);
        }
        cp_commit();
    };

    stage_load(0, 0);
    cp_wait0();
    __syncthreads();

    #pragma unroll 1
    for (int s = 0; s < NS; s++) {
        const int cb = s & 1;
        if (s + 1 < NS) stage_load(s + 1, (s + 1) & 1);

        #pragma unroll
        for (int ic = 0; ic < 16; ic++) {
            float4 v = *(const float4*)&s_x[cb][ic][oy][qx * 4];
            unsigned long long vv[4];
            vv[0] = pack2(v.x, v.x);
            vv[1] = pack2(v.y, v.y);
            vv[2] = pack2(v.z, v.z);
            vv[3] = pack2(v.w, v.w);
            // weights: 16 oc = 8 pairs = 4 x ulonglong2 (LDS.128 each)
            const ulonglong2* wp = (const ulonglong2*)&s_w[cb][ic][ocg * 16];
            #pragma unroll
            for (int q = 0; q < 4; q++) {
                ulonglong2 w2 = wp[q];
                #pragma unroll
                for (int px = 0; px < 4; px++) {
                    fma2(acc[2 * q + 0][px], w2.x, vv[px]);
                    fma2(acc[2 * q + 1][px], w2.y, vv[px]);
                }
            }
        }

        if (s + 1 < NS) {
            cp_wait0();
            __syncthreads();
        }
    }

    const int orow = tyo + oy;
    const int ocol = txo + qx * 4;
    #pragma unroll
    for (int p = 0; p < 8; p++) {
        float lo[4], hi[4];
        #pragma unroll
        for (int px = 0; px < 4; px++) unpack2(acc[p][px], lo[px], hi[px]);
        int oc0 = ocb + ocg * 16 + 2 * p;
        float bv0 = bias[oc0], bv1 = bias[oc0 + 1];
        float4 r0, r1;
        r0.x = __fadd_rn(lo[0], bv0); r0.y = __fadd_rn(lo[1], bv0);
        r0.z = __fadd_rn(lo[2], bv0); r0.w = __fadd_rn(lo[3], bv0);
        r1.x = __fadd_rn(hi[0], bv1); r1.y = __fadd_rn(hi[1], bv1);
        r1.z = __fadd_rn(hi[2], bv1); r1.w = __fadd_rn(hi[3], bv1);
        float* op0 = out + ((size_t)img * OC + oc0) * (OH * OH);
        *(float4*)&op0[orow * OH + ocol] = r0;
        *(float4*)&op0[(size_t)(OH * OH) + orow * OH + ocol] = r1;
    }
}

// ---------------------------------------------------------------------------
// det conv: 1x1, 256 -> 255, on pooled [4][256][1024]. k = ic ascending.
// ---------------------------------------------------------------------------
__global__ void __launch_bounds__(256) det_kernel(
    const float* __restrict__ pool, const float* __restrict__ wd,
    const float* __restrict__ bd, float* __restrict__ out)
{
    __shared__ float s_a[64][17];
    __shared__ float s_b[16][64];

    const int bz  = blockIdx.z;
    const int ocb = blockIdx.y * 64;
    const int pxb = blockIdx.x * 64;
    const int tid = threadIdx.x;
    const int ol0 = (tid & 15) * 4;
    const int pl0 = (tid >> 4) * 4;

    float acc[4][4];
    #pragma unroll
    for (int i = 0; i < 4; i++)
        #pragma unroll
        for (int j = 0; j < 4; j++) acc[i][j] = 0.f;

    for (int k0 = 0; k0 < 256; k0 += 16) {
        __syncthreads();
        for (int i = tid; i < 1024; i += 256) {
            int oc_l = i >> 4, kk = i & 15;
            int oc = ocb + oc_l;
            s_a[oc_l][kk] = (oc < 255) ? wd[oc * 256 + k0 + kk] : 0.f;
        }
        for (int i = tid; i < 1024; i += 256) {
            int kk = i >> 6, px_l = i & 63;
            s_b[kk][px_l] = pool[((size_t)bz * 256 + k0 + kk) * 1024 + pxb + px_l];
        }
        __syncthreads();
        #pragma unroll
        for (int kk = 0; kk < 16; kk++) {
            float a0 = s_a[ol0 + 0][kk], a1 = s_a[ol0 + 1][kk];
            float a2 = s_a[ol0 + 2][kk], a3 = s_a[ol0 + 3][kk];
            float b0 = s_b[kk][pl0 + 0], b1 = s_b[kk][pl0 + 1];
            float b2 = s_b[kk][pl0 + 2], b3 = s_b[kk][pl0 + 3];
            acc[0][0] = __fmaf_rn(a0, b0, acc[0][0]); acc[0][1] = __fmaf_rn(a0, b1, acc[0][1]);
            acc[0][2] = __fmaf_rn(a0, b2, acc[0][2]); acc[0][3] = __fmaf_rn(a0, b3, acc[0][3]);
            acc[1][0] = __fmaf_rn(a1, b0, acc[1][0]); acc[1][1] = __fmaf_rn(a1, b1, acc[1][1]);
            acc[1][2] = __fmaf_rn(a1, b2, acc[1][2]); acc[1][3] = __fmaf_rn(a1, b3, acc[1][3]);
            acc[2][0] = __fmaf_rn(a2, b0, acc[2][0]); acc[2][1] = __fmaf_rn(a2, b1, acc[2][1]);
            acc[2][2] = __fmaf_rn(a2, b2, acc[2][2]); acc[2][3] = __fmaf_rn(a2, b3, acc[2][3]);
            acc[3][0] = __fmaf_rn(a3, b0, acc[3][0]); acc[3][1] = __fmaf_rn(a3, b1, acc[3][1]);
            acc[3][2] = __fmaf_rn(a3, b2, acc[3][2]); acc[3][3] = __fmaf_rn(a3, b3, acc[3][3]);
        }
    }

    #pragma unroll
    for (int i = 0; i < 4; i++) {
        int oc = ocb + ol0 + i;
        if (oc >= 255) continue;
        float bv = bd[oc];
        #pragma unroll
        for (int j = 0; j < 4; j++)
            out[((size_t)bz * 255 + oc) * 1024 + pxb + pl0 + j] =
                __fadd_rn(acc[i][j], bv);
    }
}

// ---------------------------------------------------------------------------
extern "C" void kernel_launch(void* const* d_in, const int* in_sizes, int n_in,
                              void* d_out, int out_size)
{
    const float* x  = (const float*)d_in[0];
    const float* w1 = (const float*)d_in[1];
    const float* b1 = (const float*)d_in[2];
    const float* w2 = (const float*)d_in[3];
    const float* b2 = (const float*)d_in[4];
    const float* w3 = (const float*)d_in[5];
    const float* b3 = (const float*)d_in[6];
    const float* wd = (const float*)d_in[7];
    const float* bd = (const float*)d_in[8];
    float* out = (float*)d_out;

    float *l1, *l2, *l3, *pl, *wt2, *wt3;
    cudaGetSymbolAddress((void**)&l1, g_l1);
    cudaGetSymbolAddress((void**)&l2, g_l2);
    cudaGetSymbolAddress((void**)&l3, g_l3);
    cudaGetSymbolAddress((void**)&pl, g_pool);
    cudaGetSymbolAddress((void**)&wt2, g_wt2);
    cudaGetSymbolAddress((void**)&wt3, g_wt3);

    wtrans_kernel<<<(73728 + 255) / 256, 256>>>(w2, wt2, 128, 64);
    wtrans_kernel<<<(294912 + 255) / 256, 256>>>(w3, wt3, 256, 128);

    conv1_lif_kernel<<<dim3(64, 8, 4), 256>>>(x, w1, b1, l1);
    conv_s2_nhwc_kernel<64, 128, 128><<<dim3(16, 2, 40), 256>>>(l1, wt2, b2, l2);
    lif_kernel<<<2097152 / 256, 256>>>(l2, 2097152);
    conv_s2_nhwc_kernel<128, 256, 64><<<dim3(4, 4, 40), 256>>>(l2, wt3, b3, l3);
    lif_pool_kernel<<<1048576 / 256, 256>>>(l3, pl, 1048576);
    det_kernel<<<dim3(16, 4, 4), 256>>>(pl, wd, bd, out);
}